// round 10
// baseline (speedup 1.0000x reference)
#include <cuda_runtime.h>
#include <cuda_fp16.h>
#include <cstdint>
#include <math.h>

#define DIM   1024
#define FF    4096
#define BATCH 4
#define SEQ   2048
#define NTOK  (BATCH * SEQ)   // 8192
#define EPS   1e-5f

#define CHUNKS 64
#define CLEN   (SEQ / CHUNKS)  // 32

// ---------------- scratch (allocation-free: __device__ globals) ----------------
__device__ float2 g_stats[NTOK];             // LN1 per-token (mean, rstd)
__device__ float  g_x2[NTOK * DIM];          // residual after sconv branch
__device__ __half g_ah [NTOK * DIM];         // LN2 out (fp16)
__device__ __half g_w1h[FF * DIM];           // w1 fp16
__device__ __half g_w2h[DIM * FF];           // w2 fp16
__device__ __half g_hf [(size_t)NTOK * FF];  // FFN hidden (fp16)
__device__ float  g_cfr[BATCH * CHUNKS * DIM];
__device__ float  g_cfi[BATCH * CHUNKS * DIM];
__device__ float  g_csr[BATCH * CHUNKS * DIM];
__device__ float  g_csi[BATCH * CHUNKS * DIM];

// ======================== PTX helpers (baseline ISA, sm_80+) ========================
__device__ __forceinline__ uint32_t smem_u32(const void* p) {
    uint32_t a;
    asm("{ .reg .u64 t; cvta.to.shared.u64 t, %1; cvt.u32.u64 %0, t; }" : "=r"(a) : "l"(p));
    return a;
}
__device__ __forceinline__ void cp_async16(uint32_t s, const void* g) {
    asm volatile("cp.async.cg.shared.global [%0], [%1], 16;" :: "r"(s), "l"(g) : "memory");
}
#define CP_COMMIT() asm volatile("cp.async.commit_group;" ::: "memory")
#define CP_WAIT1()  asm volatile("cp.async.wait_group 1;" ::: "memory")

__device__ __forceinline__ void ldsm4(uint32_t* r, uint32_t addr) {
    asm volatile("ldmatrix.sync.aligned.m8n8.x4.shared.b16 {%0,%1,%2,%3}, [%4];"
                 : "=r"(r[0]), "=r"(r[1]), "=r"(r[2]), "=r"(r[3]) : "r"(addr));
}
__device__ __forceinline__ void mma16816(float* d, const uint32_t* a,
                                         uint32_t b0, uint32_t b1) {
    asm volatile(
        "mma.sync.aligned.m16n8k16.row.col.f32.f16.f16.f32 "
        "{%0,%1,%2,%3}, {%4,%5,%6,%7}, {%8,%9}, {%0,%1,%2,%3};"
        : "+f"(d[0]), "+f"(d[1]), "+f"(d[2]), "+f"(d[3])
        : "r"(a[0]), "r"(a[1]), "r"(a[2]), "r"(a[3]), "r"(b0), "r"(b1));
}

// ======================================================================
// LN1 stats: one warp per token -> (mean, rstd)
// ======================================================================
__global__ __launch_bounds__(256)
void ln_stats_kernel(const float* __restrict__ x, float2* __restrict__ stats)
{
    const int warp = threadIdx.x >> 5, lane = threadIdx.x & 31;
    const int tok = blockIdx.x * 8 + warp;
    const float4* xr = reinterpret_cast<const float4*>(x + (size_t)tok * DIM);
    float s = 0.f, sq = 0.f;
    #pragma unroll
    for (int i = 0; i < 8; ++i) {
        const float4 v = xr[lane + 32 * i];
        s  += v.x + v.y + v.z + v.w;
        sq += v.x*v.x + v.y*v.y + v.z*v.z + v.w*v.w;
    }
    #pragma unroll
    for (int o = 16; o > 0; o >>= 1) {
        s  += __shfl_xor_sync(0xffffffffu, s,  o);
        sq += __shfl_xor_sync(0xffffffffu, sq, o);
    }
    if (lane == 0) {
        const float mean = s * (1.0f / DIM);
        const float var  = sq * (1.0f / DIM) - mean * mean;
        stats[tok] = make_float2(mean, rsqrtf(var + EPS));
    }
}

// ======================================================================
// LayerNorm → fp16 output — feeds GEMM1
// ======================================================================
__global__ __launch_bounds__(256)
void ln_half_kernel(const float* __restrict__ x, const float* __restrict__ w,
                    const float* __restrict__ b, __half* __restrict__ y)
{
    const int tok = blockIdx.x;
    const int tid = threadIdx.x;
    float4 v = reinterpret_cast<const float4*>(x + (size_t)tok * DIM)[tid];
    float s  = v.x + v.y + v.z + v.w;
    float sq = v.x*v.x + v.y*v.y + v.z*v.z + v.w*v.w;
    #pragma unroll
    for (int o = 16; o > 0; o >>= 1) {
        s  += __shfl_xor_sync(0xffffffffu, s,  o);
        sq += __shfl_xor_sync(0xffffffffu, sq, o);
    }
    __shared__ float sa[8], sb[8];
    const int wid = tid >> 5, lid = tid & 31;
    if (lid == 0) { sa[wid] = s; sb[wid] = sq; }
    __syncthreads();
    if (tid < 32) {
        s  = (lid < 8) ? sa[lid] : 0.f;
        sq = (lid < 8) ? sb[lid] : 0.f;
        #pragma unroll
        for (int o = 4; o > 0; o >>= 1) {
            s  += __shfl_xor_sync(0xffffffffu, s,  o);
            sq += __shfl_xor_sync(0xffffffffu, sq, o);
        }
        if (lid == 0) { sa[0] = s; sb[0] = sq; }
    }
    __syncthreads();
    const float mean = sa[0] * (1.0f / DIM);
    const float var  = sb[0] * (1.0f / DIM) - mean * mean;
    const float rstd = rsqrtf(var + EPS);
    const float4 wv = reinterpret_cast<const float4*>(w)[tid];
    const float4 bv = reinterpret_cast<const float4*>(b)[tid];
    float o0 = (v.x - mean) * rstd * wv.x + bv.x;
    float o1 = (v.y - mean) * rstd * wv.y + bv.y;
    float o2 = (v.z - mean) * rstd * wv.z + bv.z;
    float o3 = (v.w - mean) * rstd * wv.w + bv.w;
    __half2* ph = reinterpret_cast<__half2*>(y + (size_t)tok * DIM);
    ph[tid * 2]     = __floats2half2_rn(o0, o1);
    ph[tid * 2 + 1] = __floats2half2_rn(o2, o3);
}

// ======================================================================
// fp32 -> fp16 conversion (weights)
// ======================================================================
__global__ __launch_bounds__(256)
void tofp16_kernel(const float* __restrict__ w, __half* __restrict__ o)
{
    const int i = blockIdx.x * blockDim.x + threadIdx.x;
    float4 v = reinterpret_cast<const float4*>(w)[i];
    reinterpret_cast<__half2*>(o)[2*i]   = __floats2half2_rn(v.x, v.y);
    reinterpret_cast<__half2*>(o)[2*i+1] = __floats2half2_rn(v.z, v.w);
}

// ======================================================================
// Chunked complex scan with on-the-fly h = silu(LN1(x)):
//   s[l] = p*s[l-1] + h[l], s[-1]=last
// ======================================================================
__device__ __forceinline__ void get_p(const float* pre, const float* pim, int d,
                                      float& pr, float& pi) {
    const float prr = pre[d], pir = pim[d];
    const float mag = sqrtf(prr * prr + pir * pir);
    const float scale = (mag > 0.f) ? (tanhf(mag) / mag) : 0.f;
    pr = prr * scale; pi = pir * scale;
}

__device__ __forceinline__ float fly_h(float xv, float2 st, float w, float b) {
    const float t = fmaf((xv - st.x) * st.y, w, b);
    return t / (1.f + expf(-t));
}

__global__ __launch_bounds__(128)
void scan_p1(const float* __restrict__ x, const float2* __restrict__ stats,
             const float* __restrict__ ln1w, const float* __restrict__ ln1b,
             const float* __restrict__ pre, const float* __restrict__ pim,
             float* __restrict__ cfr, float* __restrict__ cfi)
{
    const int d = blockIdx.x * 128 + threadIdx.x;
    const int c = blockIdx.y, b = blockIdx.z;
    float pr, pi; get_p(pre, pim, d, pr, pi);
    const float w = ln1w[d], bb = ln1b[d];
    float sr = 0.f, si = 0.f;
    const int tok0 = b * SEQ + c * CLEN;
    const float* xp = x + (size_t)tok0 * DIM + d;
    #pragma unroll 8
    for (int l = 0; l < CLEN; ++l) {
        const float xv = xp[(size_t)l * DIM];
        const float hv = fly_h(xv, stats[tok0 + l], w, bb);
        const float nr = fmaf(pr, sr, fmaf(-pi, si, hv));
        const float ni = fmaf(pr, si, pi * sr);
        sr = nr; si = ni;
    }
    const int idx = (b * CHUNKS + c) * DIM + d;
    cfr[idx] = sr; cfi[idx] = si;
}

__global__ __launch_bounds__(128)
void scan_p2(const float* __restrict__ pre, const float* __restrict__ pim,
             const float* __restrict__ lre, const float* __restrict__ lim,
             const float* __restrict__ cfr, const float* __restrict__ cfi,
             float* __restrict__ csr, float* __restrict__ csi)
{
    const int d = blockIdx.x * 128 + threadIdx.x;
    const int b = blockIdx.y;
    float pr, pi; get_p(pre, pim, d, pr, pi);
    float ar = pr, ai = pi;       // p^CLEN by squaring (CLEN = 2^5)
    #pragma unroll
    for (int t = 0; t < 5; ++t) {
        const float nr = ar * ar - ai * ai;
        const float ni = 2.f * ar * ai;
        ar = nr; ai = ni;
    }
    float sr = lre[d], si = lim[d];
    #pragma unroll
    for (int c = 0; c < CHUNKS; ++c) {
        const int idx = (b * CHUNKS + c) * DIM + d;
        csr[idx] = sr; csi[idx] = si;
        const float fr = cfr[idx], fi = cfi[idx];
        const float nr = fmaf(ar, sr, fmaf(-ai, si, fr));
        const float ni = fmaf(ar, si, fmaf(ai, sr, fi));
        sr = nr; si = ni;
    }
}

__global__ __launch_bounds__(128)
void scan_p3(const float* __restrict__ x, const float2* __restrict__ stats,
             const float* __restrict__ ln1w, const float* __restrict__ ln1b,
             const float* __restrict__ pre, const float* __restrict__ pim,
             const float* __restrict__ csr, const float* __restrict__ csi,
             const float* __restrict__ sc, float* __restrict__ x2)
{
    const int d = blockIdx.x * 128 + threadIdx.x;
    const int c = blockIdx.y, b = blockIdx.z;
    float pr, pi; get_p(pre, pim, d, pr, pi);
    const float w = ln1w[d], bb = ln1b[d];
    const int idx = (b * CHUNKS + c) * DIM + d;
    float sr = csr[idx], si = csi[idx];
    const float scl = sc[d];
    const int tok0 = b * SEQ + c * CLEN;
    const size_t base = (size_t)tok0 * DIM + d;
    const float* xp = x  + base;
    float*       op = x2 + base;
    #pragma unroll 8
    for (int l = 0; l < CLEN; ++l) {
        const size_t off = (size_t)l * DIM;
        const float xv = xp[off];
        const float hv = fly_h(xv, stats[tok0 + l], w, bb);
        const float nr = fmaf(pr, sr, fmaf(-pi, si, hv));
        const float ni = fmaf(pr, si, pi * sr);
        sr = nr; si = ni;
        op[off] = fmaf(sr, scl, xv);
    }
}

// ======================================================================
// fp16 HMMA GEMM: C[M,N] = A[M,K] @ B[N,K]^T  (fp32 accumulate)
// 128x128x64 block tile, 128 threads (4 warps, 2x2), warp tile 64x64,
// 3-stage cp.async pipeline, XOR-8 swizzled 128B smem rows, 2 CTAs/SM.
// Grouped-serpentine CTA rasterization (G=8) for L2 locality.
// mode 0: hf = fp16(silu(acc + bias))        (GEMM1)
// mode 1: out = acc + bias + resid (fp32)    (GEMM2)
// ======================================================================
#define BM 128
#define BN 128
#define BK 64
#define STAGE_BYTES 32768         // A 16KB + B 16KB
#define GSMEM (3 * STAGE_BYTES)   // 96 KB

__global__ __launch_bounds__(128, 2)
void gemm_f16(const __half* __restrict__ A, const __half* __restrict__ B,
              const float* __restrict__ bias, const float* __restrict__ resid,
              float* __restrict__ outF, __half* __restrict__ outH,
              int M, int N, int K, int mode)
{
    extern __shared__ char smem[];
    const uint32_t sb = smem_u32(smem);
    const int tid  = threadIdx.x;
    const int lane = tid & 31;
    const int wid  = tid >> 5;      // 0..3
    const int wr   = wid & 1;       // warp M half (64 rows)
    const int wc   = wid >> 1;      // warp N half (64 cols)

    // grouped rasterization: groups of 8 M-tiles sweep N together
    const int nbx = gridDim.x;
    const int bid = blockIdx.y * nbx + blockIdx.x;
    const int gsz = 8 * nbx;
    const int g   = bid / gsz;
    const int rem = bid - g * gsz;
    const int by  = g * 8 + (rem & 7);
    const int bx  = rem >> 3;
    const int m0 = by * BM;
    const int n0 = bx * BN;

    // cp.async geometry: per stage, per thread: 8 chunks A + 8 chunks B (16B each)
    int ldrow[8], ldq[8]; uint32_t ldso[8];
    #pragma unroll
    for (int i = 0; i < 8; ++i) {
        const int idx = tid + 128 * i;   // 0..1023
        ldrow[i] = idx >> 3;
        ldq[i]   = idx & 7;
        ldso[i]  = (uint32_t)(ldrow[i] * 128 + ((ldq[i] ^ (ldrow[i] & 7)) << 4));
    }

    const int NKC = K >> 6;

    // ldmatrix geometry
    const int arow_b = wr * 64 + (lane & 15);
    const int brow_b = wc * 64 + (lane & 15);
    const int kh8    = lane >> 4;     // 0/1 -> k-half chunk

    float acc[4][8][4];
    #pragma unroll
    for (int mi = 0; mi < 4; ++mi)
        #pragma unroll
        for (int n8 = 0; n8 < 8; ++n8)
            #pragma unroll
            for (int e = 0; e < 4; ++e) acc[mi][n8][e] = 0.f;

    auto load_stage = [&](int kt, int slot) {
        const uint32_t aB = sb + slot * STAGE_BYTES;
        const uint32_t bB = aB + 16384;
        const int k0 = kt * BK;
        #pragma unroll
        for (int i = 0; i < 8; ++i) {
            cp_async16(aB + ldso[i], A + (size_t)(m0 + ldrow[i]) * K + k0 + ldq[i] * 8);
            cp_async16(bB + ldso[i], B + (size_t)(n0 + ldrow[i]) * K + k0 + ldq[i] * 8);
        }
    };

    load_stage(0, 0); CP_COMMIT();
    load_stage(1, 1); CP_COMMIT();

    int slot = 0;
    for (int kt = 0; kt < NKC; ++kt) {
        CP_WAIT1();
        __syncthreads();
        if (kt + 2 < NKC) load_stage(kt + 2, (slot + 2) % 3);
        CP_COMMIT();

        const uint32_t aBase = sb + slot * STAGE_BYTES;
        const uint32_t bBase = aBase + 16384;
        #pragma unroll
        for (int s = 0; s < 4; ++s) {
            uint32_t af[4][4], bf[4][4];
            #pragma unroll
            for (int mi = 0; mi < 4; ++mi) {
                const int r = arow_b + mi * 16;
                const uint32_t q = (uint32_t)((s * 2 + kh8) ^ (r & 7));
                ldsm4(af[mi], aBase + (uint32_t)r * 128 + q * 16);
            }
            #pragma unroll
            for (int ni = 0; ni < 4; ++ni) {
                const int r = brow_b + ni * 16;
                const uint32_t q = (uint32_t)((s * 2 + kh8) ^ (r & 7));
                ldsm4(bf[ni], bBase + (uint32_t)r * 128 + q * 16);
            }
            #pragma unroll
            for (int mi = 0; mi < 4; ++mi)
                #pragma unroll
                for (int n8 = 0; n8 < 8; ++n8)
                    mma16816(acc[mi][n8], af[mi],
                             bf[n8 >> 1][n8 & 1], bf[n8 >> 1][(n8 & 1) + 2]);
        }
        slot = (slot + 1) % 3;
    }

    // ---- epilogue ----
    const int rq = lane >> 2;          // 0..7
    const int cq = (lane & 3) * 2;
    #pragma unroll
    for (int mi = 0; mi < 4; ++mi) {
        const int r0 = m0 + wr * 64 + mi * 16 + rq;
        #pragma unroll
        for (int n8 = 0; n8 < 8; ++n8) {
            const int c = n0 + wc * 64 + n8 * 8 + cq;
            const float b0 = bias[c], b1 = bias[c + 1];
            float d0 = acc[mi][n8][0] + b0;
            float d1 = acc[mi][n8][1] + b1;
            float d2 = acc[mi][n8][2] + b0;
            float d3 = acc[mi][n8][3] + b1;
            const size_t o0 = (size_t)r0 * N + c;
            const size_t o1 = (size_t)(r0 + 8) * N + c;
            if (mode == 0) {
                d0 *= 1.0f / (1.0f + expf(-d0));
                d1 *= 1.0f / (1.0f + expf(-d1));
                d2 *= 1.0f / (1.0f + expf(-d2));
                d3 *= 1.0f / (1.0f + expf(-d3));
                *reinterpret_cast<__half2*>(outH + o0) = __floats2half2_rn(d0, d1);
                *reinterpret_cast<__half2*>(outH + o1) = __floats2half2_rn(d2, d3);
            } else {
                const float2 rv0 = *reinterpret_cast<const float2*>(resid + o0);
                const float2 rv1 = *reinterpret_cast<const float2*>(resid + o1);
                float2 w0 = {d0 + rv0.x, d1 + rv0.y};
                float2 w1 = {d2 + rv1.x, d3 + rv1.y};
                *reinterpret_cast<float2*>(outF + o0) = w0;
                *reinterpret_cast<float2*>(outF + o1) = w1;
            }
        }
    }
}

// ======================================================================
// launch
// ======================================================================
extern "C" void kernel_launch(void* const* d_in, const int* in_sizes, int n_in,
                              void* d_out, int out_size)
{
    const float* x     = (const float*)d_in[0];
    const float* ln1_w = (const float*)d_in[1];
    const float* ln1_b = (const float*)d_in[2];
    const float* ln2_w = (const float*)d_in[3];
    const float* ln2_b = (const float*)d_in[4];
    const float* sclin = (const float*)d_in[5];
    const float* p_re  = (const float*)d_in[6];
    const float* p_im  = (const float*)d_in[7];
    const float* l_re  = (const float*)d_in[8];
    const float* l_im  = (const float*)d_in[9];
    const float* w1    = (const float*)d_in[10];
    const float* b1    = (const float*)d_in[11];
    const float* w2    = (const float*)d_in[12];
    const float* b2    = (const float*)d_in[13];
    float* out = (float*)d_out;

    float *x2, *cfr, *cfi, *csr, *csi;
    float2* stats;
    __half *ah, *w1h, *w2h, *hf;
    cudaGetSymbolAddress((void**)&stats, g_stats);
    cudaGetSymbolAddress((void**)&x2,  g_x2);
    cudaGetSymbolAddress((void**)&ah,  g_ah);
    cudaGetSymbolAddress((void**)&w1h, g_w1h);
    cudaGetSymbolAddress((void**)&w2h, g_w2h);
    cudaGetSymbolAddress((void**)&hf,  g_hf);
    cudaGetSymbolAddress((void**)&cfr, g_cfr);
    cudaGetSymbolAddress((void**)&cfi, g_cfi);
    cudaGetSymbolAddress((void**)&csr, g_csr);
    cudaGetSymbolAddress((void**)&csi, g_csi);

    cudaFuncSetAttribute(gemm_f16, cudaFuncAttributeMaxDynamicSharedMemorySize, GSMEM);

    // weight conversions (independent of the data path)
    tofp16_kernel<<<(FF * DIM / 4) / 256, 256>>>(w1, w1h);
    tofp16_kernel<<<(DIM * FF / 4) / 256, 256>>>(w2, w2h);

    // 1) LN1 per-token stats
    ln_stats_kernel<<<NTOK / 8, 256>>>(x, stats);

    // 2) chunked scan with on-the-fly h: x2 = Re(scan(silu(LN1(x)))) * sc_lin + x
    scan_p1<<<dim3(DIM / 128, CHUNKS, BATCH), 128>>>(x, stats, ln1_w, ln1_b,
                                                     p_re, p_im, cfr, cfi);
    scan_p2<<<dim3(DIM / 128, BATCH), 128>>>(p_re, p_im, l_re, l_im, cfr, cfi, csr, csi);
    scan_p3<<<dim3(DIM / 128, CHUNKS, BATCH), 128>>>(x, stats, ln1_w, ln1_b,
                                                     p_re, p_im, csr, csi, sclin, x2);

    // 3) LN2(x2) -> fp16
    ln_half_kernel<<<NTOK, 256>>>(x2, ln2_w, ln2_b, ah);

    // 4) hf = fp16(silu(ah @ w1^T + b1))   [8192,4096]
    gemm_f16<<<dim3(FF / BN, NTOK / BM), 128, GSMEM>>>(
        ah, w1h, b1, nullptr, nullptr, hf, NTOK, FF, DIM, 0);

    // 5) out = hf @ w2^T + b2 + x2         [8192,1024]
    gemm_f16<<<dim3(DIM / BN, NTOK / BM), 128, GSMEM>>>(
        hf, w2h, b2, x2, out, nullptr, NTOK, DIM, FF, 1);
}

// round 11
// speedup vs baseline: 1.0561x; 1.0561x over previous
#include <cuda_runtime.h>
#include <cuda_fp16.h>
#include <cstdint>
#include <math.h>

#define DIM   1024
#define FF    4096
#define BATCH 4
#define SEQ   2048
#define NTOK  (BATCH * SEQ)   // 8192
#define EPS   1e-5f

#define CHUNKS 64
#define CLEN   (SEQ / CHUNKS)  // 32

// ---------------- scratch (allocation-free: __device__ globals) ----------------
__device__ float  g_h [NTOK * DIM];          // LN1+silu output (fp32, scan input)
__device__ float  g_x2[NTOK * DIM];          // residual after sconv branch
__device__ __half g_ah [NTOK * DIM];         // LN2 out (fp16)
__device__ __half g_w1h[FF * DIM];           // w1 fp16
__device__ __half g_w2h[DIM * FF];           // w2 fp16
__device__ __half g_hf [(size_t)NTOK * FF];  // FFN hidden (fp16)
__device__ float  g_cfr[BATCH * CHUNKS * DIM];
__device__ float  g_cfi[BATCH * CHUNKS * DIM];
__device__ float  g_csr[BATCH * CHUNKS * DIM];
__device__ float  g_csi[BATCH * CHUNKS * DIM];

// ======================== PTX helpers (baseline ISA, sm_80+) ========================
__device__ __forceinline__ uint32_t smem_u32(const void* p) {
    uint32_t a;
    asm("{ .reg .u64 t; cvta.to.shared.u64 t, %1; cvt.u32.u64 %0, t; }" : "=r"(a) : "l"(p));
    return a;
}
__device__ __forceinline__ void cp_async16(uint32_t s, const void* g) {
    asm volatile("cp.async.cg.shared.global [%0], [%1], 16;" :: "r"(s), "l"(g) : "memory");
}
#define CP_COMMIT() asm volatile("cp.async.commit_group;" ::: "memory")
#define CP_WAIT1()  asm volatile("cp.async.wait_group 1;" ::: "memory")

__device__ __forceinline__ void ldsm4(uint32_t* r, uint32_t addr) {
    asm volatile("ldmatrix.sync.aligned.m8n8.x4.shared.b16 {%0,%1,%2,%3}, [%4];"
                 : "=r"(r[0]), "=r"(r[1]), "=r"(r[2]), "=r"(r[3]) : "r"(addr));
}
__device__ __forceinline__ void mma16816(float* d, const uint32_t* a,
                                         uint32_t b0, uint32_t b1) {
    asm volatile(
        "mma.sync.aligned.m16n8k16.row.col.f32.f16.f16.f32 "
        "{%0,%1,%2,%3}, {%4,%5,%6,%7}, {%8,%9}, {%0,%1,%2,%3};"
        : "+f"(d[0]), "+f"(d[1]), "+f"(d[2]), "+f"(d[3])
        : "r"(a[0]), "r"(a[1]), "r"(a[2]), "r"(a[3]), "r"(b0), "r"(b1));
}

// ======================================================================
// LayerNorm + SiLU (fp32 out) — feeds the scan
// ======================================================================
__global__ __launch_bounds__(256)
void ln_silu_kernel(const float* __restrict__ x, const float* __restrict__ w,
                    const float* __restrict__ b, float* __restrict__ y)
{
    const int tok = blockIdx.x;
    const int tid = threadIdx.x;
    float4 v = reinterpret_cast<const float4*>(x + (size_t)tok * DIM)[tid];
    float s  = v.x + v.y + v.z + v.w;
    float sq = v.x*v.x + v.y*v.y + v.z*v.z + v.w*v.w;
    #pragma unroll
    for (int o = 16; o > 0; o >>= 1) {
        s  += __shfl_xor_sync(0xffffffffu, s,  o);
        sq += __shfl_xor_sync(0xffffffffu, sq, o);
    }
    __shared__ float sa[8], sb[8];
    const int wid = tid >> 5, lid = tid & 31;
    if (lid == 0) { sa[wid] = s; sb[wid] = sq; }
    __syncthreads();
    if (tid < 32) {
        s  = (lid < 8) ? sa[lid] : 0.f;
        sq = (lid < 8) ? sb[lid] : 0.f;
        #pragma unroll
        for (int o = 4; o > 0; o >>= 1) {
            s  += __shfl_xor_sync(0xffffffffu, s,  o);
            sq += __shfl_xor_sync(0xffffffffu, sq, o);
        }
        if (lid == 0) { sa[0] = s; sb[0] = sq; }
    }
    __syncthreads();
    const float mean = sa[0] * (1.0f / DIM);
    const float var  = sb[0] * (1.0f / DIM) - mean * mean;
    const float rstd = rsqrtf(var + EPS);
    const float4 wv = reinterpret_cast<const float4*>(w)[tid];
    const float4 bv = reinterpret_cast<const float4*>(b)[tid];
    float4 o;
    o.x = (v.x - mean) * rstd * wv.x + bv.x;
    o.y = (v.y - mean) * rstd * wv.y + bv.y;
    o.z = (v.z - mean) * rstd * wv.z + bv.z;
    o.w = (v.w - mean) * rstd * wv.w + bv.w;
    o.x *= 1.0f / (1.0f + expf(-o.x));
    o.y *= 1.0f / (1.0f + expf(-o.y));
    o.z *= 1.0f / (1.0f + expf(-o.z));
    o.w *= 1.0f / (1.0f + expf(-o.w));
    reinterpret_cast<float4*>(y + (size_t)tok * DIM)[tid] = o;
}

// ======================================================================
// LayerNorm → fp16 output — feeds GEMM1
// ======================================================================
__global__ __launch_bounds__(256)
void ln_half_kernel(const float* __restrict__ x, const float* __restrict__ w,
                    const float* __restrict__ b, __half* __restrict__ y)
{
    const int tok = blockIdx.x;
    const int tid = threadIdx.x;
    float4 v = reinterpret_cast<const float4*>(x + (size_t)tok * DIM)[tid];
    float s  = v.x + v.y + v.z + v.w;
    float sq = v.x*v.x + v.y*v.y + v.z*v.z + v.w*v.w;
    #pragma unroll
    for (int o = 16; o > 0; o >>= 1) {
        s  += __shfl_xor_sync(0xffffffffu, s,  o);
        sq += __shfl_xor_sync(0xffffffffu, sq, o);
    }
    __shared__ float sa[8], sb[8];
    const int wid = tid >> 5, lid = tid & 31;
    if (lid == 0) { sa[wid] = s; sb[wid] = sq; }
    __syncthreads();
    if (tid < 32) {
        s  = (lid < 8) ? sa[lid] : 0.f;
        sq = (lid < 8) ? sb[lid] : 0.f;
        #pragma unroll
        for (int o = 4; o > 0; o >>= 1) {
            s  += __shfl_xor_sync(0xffffffffu, s,  o);
            sq += __shfl_xor_sync(0xffffffffu, sq, o);
        }
        if (lid == 0) { sa[0] = s; sb[0] = sq; }
    }
    __syncthreads();
    const float mean = sa[0] * (1.0f / DIM);
    const float var  = sb[0] * (1.0f / DIM) - mean * mean;
    const float rstd = rsqrtf(var + EPS);
    const float4 wv = reinterpret_cast<const float4*>(w)[tid];
    const float4 bv = reinterpret_cast<const float4*>(b)[tid];
    float o0 = (v.x - mean) * rstd * wv.x + bv.x;
    float o1 = (v.y - mean) * rstd * wv.y + bv.y;
    float o2 = (v.z - mean) * rstd * wv.z + bv.z;
    float o3 = (v.w - mean) * rstd * wv.w + bv.w;
    __half2* ph = reinterpret_cast<__half2*>(y + (size_t)tok * DIM);
    ph[tid * 2]     = __floats2half2_rn(o0, o1);
    ph[tid * 2 + 1] = __floats2half2_rn(o2, o3);
}

// ======================================================================
// fp32 -> fp16 conversion (weights)
// ======================================================================
__global__ __launch_bounds__(256)
void tofp16_kernel(const float* __restrict__ w, __half* __restrict__ o)
{
    const int i = blockIdx.x * blockDim.x + threadIdx.x;
    float4 v = reinterpret_cast<const float4*>(w)[i];
    reinterpret_cast<__half2*>(o)[2*i]   = __floats2half2_rn(v.x, v.y);
    reinterpret_cast<__half2*>(o)[2*i+1] = __floats2half2_rn(v.z, v.w);
}

// ======================================================================
// Chunked complex scan: s[l] = p*s[l-1] + h[l], s[-1]=last
// ======================================================================
__device__ __forceinline__ void get_p(const float* pre, const float* pim, int d,
                                      float& pr, float& pi) {
    const float prr = pre[d], pir = pim[d];
    const float mag = sqrtf(prr * prr + pir * pir);
    const float scale = (mag > 0.f) ? (tanhf(mag) / mag) : 0.f;
    pr = prr * scale; pi = pir * scale;
}

__global__ __launch_bounds__(128)
void scan_p1(const float* __restrict__ h, const float* __restrict__ pre,
             const float* __restrict__ pim,
             float* __restrict__ cfr, float* __restrict__ cfi)
{
    const int d = blockIdx.x * 128 + threadIdx.x;
    const int c = blockIdx.y, b = blockIdx.z;
    float pr, pi; get_p(pre, pim, d, pr, pi);
    float sr = 0.f, si = 0.f;
    const float* hp = h + ((size_t)b * SEQ + (size_t)c * CLEN) * DIM + d;
    #pragma unroll 8
    for (int l = 0; l < CLEN; ++l) {
        const float hv = hp[(size_t)l * DIM];
        const float nr = fmaf(pr, sr, fmaf(-pi, si, hv));
        const float ni = fmaf(pr, si, pi * sr);
        sr = nr; si = ni;
    }
    const int idx = (b * CHUNKS + c) * DIM + d;
    cfr[idx] = sr; cfi[idx] = si;
}

__global__ __launch_bounds__(128)
void scan_p2(const float* __restrict__ pre, const float* __restrict__ pim,
             const float* __restrict__ lre, const float* __restrict__ lim,
             const float* __restrict__ cfr, const float* __restrict__ cfi,
             float* __restrict__ csr, float* __restrict__ csi)
{
    const int d = blockIdx.x * 128 + threadIdx.x;
    const int b = blockIdx.y;
    float pr, pi; get_p(pre, pim, d, pr, pi);
    float ar = pr, ai = pi;       // p^CLEN by squaring (CLEN = 2^5)
    #pragma unroll
    for (int t = 0; t < 5; ++t) {
        const float nr = ar * ar - ai * ai;
        const float ni = 2.f * ar * ai;
        ar = nr; ai = ni;
    }
    float sr = lre[d], si = lim[d];
    #pragma unroll
    for (int c = 0; c < CHUNKS; ++c) {
        const int idx = (b * CHUNKS + c) * DIM + d;
        csr[idx] = sr; csi[idx] = si;
        const float fr = cfr[idx], fi = cfi[idx];
        const float nr = fmaf(ar, sr, fmaf(-ai, si, fr));
        const float ni = fmaf(ar, si, fmaf(ai, sr, fi));
        sr = nr; si = ni;
    }
}

__global__ __launch_bounds__(128)
void scan_p3(const float* __restrict__ h, const float* __restrict__ x,
             const float* __restrict__ pre, const float* __restrict__ pim,
             const float* __restrict__ csr, const float* __restrict__ csi,
             const float* __restrict__ sc, float* __restrict__ x2)
{
    const int d = blockIdx.x * 128 + threadIdx.x;
    const int c = blockIdx.y, b = blockIdx.z;
    float pr, pi; get_p(pre, pim, d, pr, pi);
    const int idx = (b * CHUNKS + c) * DIM + d;
    float sr = csr[idx], si = csi[idx];
    const float scl = sc[d];
    const size_t base = ((size_t)b * SEQ + (size_t)c * CLEN) * DIM + d;
    const float* hp = h + base;
    const float* xp = x + base;
    float*       op = x2 + base;
    #pragma unroll 8
    for (int l = 0; l < CLEN; ++l) {
        const size_t off = (size_t)l * DIM;
        const float hv = hp[off];
        const float xv = xp[off];
        const float nr = fmaf(pr, sr, fmaf(-pi, si, hv));
        const float ni = fmaf(pr, si, pi * sr);
        sr = nr; si = ni;
        op[off] = fmaf(sr, scl, xv);
    }
}

// ======================================================================
// fp16 HMMA GEMM: C[M,N] = A[M,K] @ B[N,K]^T  (fp32 accumulate)
// 128x128x64 block tile, 256 threads, warp tile 32x64 (4x2 warps),
// 3-stage cp.async pipeline, XOR-8 swizzled 128B smem rows, 2 CTAs/SM.
// Grouped-serpentine CTA rasterization (G=8) for L2 locality.
// mode 0: hf = fp16(silu(acc + bias))        (GEMM1)
// mode 1: out = acc + bias + resid (fp32)    (GEMM2)
// ======================================================================
#define BM 128
#define BN 128
#define BK 64
#define STAGE_BYTES 32768         // A 16KB + B 16KB
#define GSMEM (3 * STAGE_BYTES)   // 96 KB

__global__ __launch_bounds__(256, 2)
void gemm_f16(const __half* __restrict__ A, const __half* __restrict__ B,
              const float* __restrict__ bias, const float* __restrict__ resid,
              float* __restrict__ outF, __half* __restrict__ outH,
              int M, int N, int K, int mode)
{
    extern __shared__ char smem[];
    const uint32_t sb = smem_u32(smem);
    const int tid  = threadIdx.x;
    const int lane = tid & 31;
    const int wid  = tid >> 5;
    const int wr   = wid & 3;       // warp M group (32 rows)
    const int wc   = wid >> 2;      // warp N group (64 cols)

    // grouped rasterization: groups of 8 M-tiles sweep N together
    const int nbx = gridDim.x;
    const int bid = blockIdx.y * nbx + blockIdx.x;
    const int gsz = 8 * nbx;
    const int g   = bid / gsz;
    const int rem = bid - g * gsz;
    const int by  = g * 8 + (rem & 7);
    const int bx  = rem >> 3;
    const int m0 = by * BM;
    const int n0 = bx * BN;

    // cp.async geometry: per stage, per thread: 4 chunks A + 4 chunks B (16B each)
    int ldrow[4], ldq[4]; uint32_t ldso[4];
    #pragma unroll
    for (int i = 0; i < 4; ++i) {
        const int idx = tid + 256 * i;   // 0..1023
        ldrow[i] = idx >> 3;
        ldq[i]   = idx & 7;
        ldso[i]  = (uint32_t)(ldrow[i] * 128 + ((ldq[i] ^ (ldrow[i] & 7)) << 4));
    }

    const int NKC = K >> 6;

    // ldmatrix geometry
    const int arow_b = wr * 32 + (lane & 15);
    const int brow_b = wc * 64 + (lane & 15);
    const int kh8    = lane >> 4;     // 0/1 -> k-halves chunk

    float acc[2][8][4];
    #pragma unroll
    for (int mi = 0; mi < 2; ++mi)
        #pragma unroll
        for (int n8 = 0; n8 < 8; ++n8)
            #pragma unroll
            for (int e = 0; e < 4; ++e) acc[mi][n8][e] = 0.f;

    auto load_stage = [&](int kt, int slot) {
        const uint32_t aB = sb + slot * STAGE_BYTES;
        const uint32_t bB = aB + 16384;
        const int k0 = kt * BK;
        #pragma unroll
        for (int i = 0; i < 4; ++i) {
            cp_async16(aB + ldso[i], A + (size_t)(m0 + ldrow[i]) * K + k0 + ldq[i] * 8);
            cp_async16(bB + ldso[i], B + (size_t)(n0 + ldrow[i]) * K + k0 + ldq[i] * 8);
        }
    };

    load_stage(0, 0); CP_COMMIT();
    load_stage(1, 1); CP_COMMIT();

    int slot = 0;
    for (int kt = 0; kt < NKC; ++kt) {
        CP_WAIT1();
        __syncthreads();
        if (kt + 2 < NKC) load_stage(kt + 2, (slot + 2) % 3);
        CP_COMMIT();

        const uint32_t aBase = sb + slot * STAGE_BYTES;
        const uint32_t bBase = aBase + 16384;
        #pragma unroll
        for (int s = 0; s < 4; ++s) {
            uint32_t af[2][4], bf[4][4];
            #pragma unroll
            for (int mi = 0; mi < 2; ++mi) {
                const int r = arow_b + mi * 16;
                const uint32_t q = (uint32_t)((s * 2 + kh8) ^ (r & 7));
                ldsm4(af[mi], aBase + (uint32_t)r * 128 + q * 16);
            }
            #pragma unroll
            for (int ni = 0; ni < 4; ++ni) {
                const int r = brow_b + ni * 16;
                const uint32_t q = (uint32_t)((s * 2 + kh8) ^ (r & 7));
                ldsm4(bf[ni], bBase + (uint32_t)r * 128 + q * 16);
            }
            #pragma unroll
            for (int mi = 0; mi < 2; ++mi)
                #pragma unroll
                for (int n8 = 0; n8 < 8; ++n8)
                    mma16816(acc[mi][n8], af[mi],
                             bf[n8 >> 1][n8 & 1], bf[n8 >> 1][(n8 & 1) + 2]);
        }
        slot = (slot + 1) % 3;
    }

    // ---- epilogue ----
    const int rq = lane >> 2;          // 0..7
    const int cq = (lane & 3) * 2;
    #pragma unroll
    for (int mi = 0; mi < 2; ++mi) {
        const int r0 = m0 + wr * 32 + mi * 16 + rq;
        #pragma unroll
        for (int n8 = 0; n8 < 8; ++n8) {
            const int c = n0 + wc * 64 + n8 * 8 + cq;
            const float b0 = bias[c], b1 = bias[c + 1];
            float d0 = acc[mi][n8][0] + b0;
            float d1 = acc[mi][n8][1] + b1;
            float d2 = acc[mi][n8][2] + b0;
            float d3 = acc[mi][n8][3] + b1;
            const size_t o0 = (size_t)r0 * N + c;
            const size_t o1 = (size_t)(r0 + 8) * N + c;
            if (mode == 0) {
                d0 *= 1.0f / (1.0f + expf(-d0));
                d1 *= 1.0f / (1.0f + expf(-d1));
                d2 *= 1.0f / (1.0f + expf(-d2));
                d3 *= 1.0f / (1.0f + expf(-d3));
                *reinterpret_cast<__half2*>(outH + o0) = __floats2half2_rn(d0, d1);
                *reinterpret_cast<__half2*>(outH + o1) = __floats2half2_rn(d2, d3);
            } else {
                const float2 rv0 = *reinterpret_cast<const float2*>(resid + o0);
                const float2 rv1 = *reinterpret_cast<const float2*>(resid + o1);
                float2 w0 = {d0 + rv0.x, d1 + rv0.y};
                float2 w1 = {d2 + rv1.x, d3 + rv1.y};
                *reinterpret_cast<float2*>(outF + o0) = w0;
                *reinterpret_cast<float2*>(outF + o1) = w1;
            }
        }
    }
}

// ======================================================================
// launch
// ======================================================================
extern "C" void kernel_launch(void* const* d_in, const int* in_sizes, int n_in,
                              void* d_out, int out_size)
{
    const float* x     = (const float*)d_in[0];
    const float* ln1_w = (const float*)d_in[1];
    const float* ln1_b = (const float*)d_in[2];
    const float* ln2_w = (const float*)d_in[3];
    const float* ln2_b = (const float*)d_in[4];
    const float* sclin = (const float*)d_in[5];
    const float* p_re  = (const float*)d_in[6];
    const float* p_im  = (const float*)d_in[7];
    const float* l_re  = (const float*)d_in[8];
    const float* l_im  = (const float*)d_in[9];
    const float* w1    = (const float*)d_in[10];
    const float* b1    = (const float*)d_in[11];
    const float* w2    = (const float*)d_in[12];
    const float* b2    = (const float*)d_in[13];
    float* out = (float*)d_out;

    float *h, *x2, *cfr, *cfi, *csr, *csi;
    __half *ah, *w1h, *w2h, *hf;
    cudaGetSymbolAddress((void**)&h,   g_h);
    cudaGetSymbolAddress((void**)&x2,  g_x2);
    cudaGetSymbolAddress((void**)&ah,  g_ah);
    cudaGetSymbolAddress((void**)&w1h, g_w1h);
    cudaGetSymbolAddress((void**)&w2h, g_w2h);
    cudaGetSymbolAddress((void**)&hf,  g_hf);
    cudaGetSymbolAddress((void**)&cfr, g_cfr);
    cudaGetSymbolAddress((void**)&cfi, g_cfi);
    cudaGetSymbolAddress((void**)&csr, g_csr);
    cudaGetSymbolAddress((void**)&csi, g_csi);

    cudaFuncSetAttribute(gemm_f16, cudaFuncAttributeMaxDynamicSharedMemorySize, GSMEM);

    // weight conversions (independent of the data path)
    tofp16_kernel<<<(FF * DIM / 4) / 256, 256>>>(w1, w1h);
    tofp16_kernel<<<(DIM * FF / 4) / 256, 256>>>(w2, w2h);

    // 1) h = silu(LN1(x))
    ln_silu_kernel<<<NTOK, 256>>>(x, ln1_w, ln1_b, h);

    // 2) chunked scan: x2 = Re(scan(h)) * sc_lin + x
    scan_p1<<<dim3(DIM / 128, CHUNKS, BATCH), 128>>>(h, p_re, p_im, cfr, cfi);
    scan_p2<<<dim3(DIM / 128, BATCH), 128>>>(p_re, p_im, l_re, l_im, cfr, cfi, csr, csi);
    scan_p3<<<dim3(DIM / 128, CHUNKS, BATCH), 128>>>(h, x, p_re, p_im, csr, csi, sclin, x2);

    // 3) LN2(x2) -> fp16
    ln_half_kernel<<<NTOK, 256>>>(x2, ln2_w, ln2_b, ah);

    // 4) hf = fp16(silu(ah @ w1^T + b1))   [8192,4096]
    gemm_f16<<<dim3(FF / BN, NTOK / BM), 256, GSMEM>>>(
        ah, w1h, b1, nullptr, nullptr, hf, NTOK, FF, DIM, 0);

    // 5) out = hf @ w2^T + b2 + x2         [8192,1024]
    gemm_f16<<<dim3(DIM / BN, NTOK / BM), 256, GSMEM>>>(
        hf, w2h, b2, x2, out, nullptr, NTOK, DIM, FF, 1);
}

// round 13
// speedup vs baseline: 1.0594x; 1.0031x over previous
#include <cuda_runtime.h>
#include <cuda_fp16.h>
#include <cstdint>
#include <math.h>

#define DIM   1024
#define FF    4096
#define BATCH 4
#define SEQ   2048
#define NTOK  (BATCH * SEQ)   // 8192
#define EPS   1e-5f

#define CHUNKS 64
#define CLEN   (SEQ / CHUNKS)  // 32

// ---------------- scratch (allocation-free: __device__ globals) ----------------
__device__ __half g_h [NTOK * DIM];          // LN1+silu output (fp16, scan input)
__device__ float  g_x2[NTOK * DIM];          // residual after sconv branch
__device__ __half g_ah [NTOK * DIM];         // LN2 out (fp16)
__device__ __half g_w1h[FF * DIM];           // w1 fp16
__device__ __half g_w2h[DIM * FF];           // w2 fp16
__device__ __half g_hf [(size_t)NTOK * FF];  // FFN hidden (fp16)
__device__ float  g_cfr[BATCH * CHUNKS * DIM];
__device__ float  g_cfi[BATCH * CHUNKS * DIM];
__device__ float  g_csr[BATCH * CHUNKS * DIM];
__device__ float  g_csi[BATCH * CHUNKS * DIM];

// ======================== PTX helpers (baseline ISA, sm_80+) ========================
__device__ __forceinline__ uint32_t smem_u32(const void* p) {
    uint32_t a;
    asm("{ .reg .u64 t; cvta.to.shared.u64 t, %1; cvt.u32.u64 %0, t; }" : "=r"(a) : "l"(p));
    return a;
}
__device__ __forceinline__ void cp_async16(uint32_t s, const void* g) {
    asm volatile("cp.async.cg.shared.global [%0], [%1], 16;" :: "r"(s), "l"(g) : "memory");
}
#define CP_COMMIT() asm volatile("cp.async.commit_group;" ::: "memory")
#define CP_WAIT1()  asm volatile("cp.async.wait_group 1;" ::: "memory")

__device__ __forceinline__ void ldsm4(uint32_t* r, uint32_t addr) {
    asm volatile("ldmatrix.sync.aligned.m8n8.x4.shared.b16 {%0,%1,%2,%3}, [%4];"
                 : "=r"(r[0]), "=r"(r[1]), "=r"(r[2]), "=r"(r[3]) : "r"(addr));
}
__device__ __forceinline__ void mma16816(float* d, const uint32_t* a,
                                         uint32_t b0, uint32_t b1) {
    asm volatile(
        "mma.sync.aligned.m16n8k16.row.col.f32.f16.f16.f32 "
        "{%0,%1,%2,%3}, {%4,%5,%6,%7}, {%8,%9}, {%0,%1,%2,%3};"
        : "+f"(d[0]), "+f"(d[1]), "+f"(d[2]), "+f"(d[3])
        : "r"(a[0]), "r"(a[1]), "r"(a[2]), "r"(a[3]), "r"(b0), "r"(b1));
}

// ======================================================================
// LayerNorm + SiLU (fp16 out) — feeds the scan
// ======================================================================
__global__ __launch_bounds__(256)
void ln_silu_kernel(const float* __restrict__ x, const float* __restrict__ w,
                    const float* __restrict__ b, __half* __restrict__ y)
{
    const int tok = blockIdx.x;
    const int tid = threadIdx.x;
    float4 v = reinterpret_cast<const float4*>(x + (size_t)tok * DIM)[tid];
    float s  = v.x + v.y + v.z + v.w;
    float sq = v.x*v.x + v.y*v.y + v.z*v.z + v.w*v.w;
    #pragma unroll
    for (int o = 16; o > 0; o >>= 1) {
        s  += __shfl_xor_sync(0xffffffffu, s,  o);
        sq += __shfl_xor_sync(0xffffffffu, sq, o);
    }
    __shared__ float sa[8], sb[8];
    const int wid = tid >> 5, lid = tid & 31;
    if (lid == 0) { sa[wid] = s; sb[wid] = sq; }
    __syncthreads();
    if (tid < 32) {
        s  = (lid < 8) ? sa[lid] : 0.f;
        sq = (lid < 8) ? sb[lid] : 0.f;
        #pragma unroll
        for (int o = 4; o > 0; o >>= 1) {
            s  += __shfl_xor_sync(0xffffffffu, s,  o);
            sq += __shfl_xor_sync(0xffffffffu, sq, o);
        }
        if (lid == 0) { sa[0] = s; sb[0] = sq; }
    }
    __syncthreads();
    const float mean = sa[0] * (1.0f / DIM);
    const float var  = sb[0] * (1.0f / DIM) - mean * mean;
    const float rstd = rsqrtf(var + EPS);
    const float4 wv = reinterpret_cast<const float4*>(w)[tid];
    const float4 bv = reinterpret_cast<const float4*>(b)[tid];
    float o0 = (v.x - mean) * rstd * wv.x + bv.x;
    float o1 = (v.y - mean) * rstd * wv.y + bv.y;
    float o2 = (v.z - mean) * rstd * wv.z + bv.z;
    float o3 = (v.w - mean) * rstd * wv.w + bv.w;
    o0 *= 1.0f / (1.0f + expf(-o0));
    o1 *= 1.0f / (1.0f + expf(-o1));
    o2 *= 1.0f / (1.0f + expf(-o2));
    o3 *= 1.0f / (1.0f + expf(-o3));
    __half2* ph = reinterpret_cast<__half2*>(y + (size_t)tok * DIM);
    ph[tid * 2]     = __floats2half2_rn(o0, o1);
    ph[tid * 2 + 1] = __floats2half2_rn(o2, o3);
}

// ======================================================================
// LayerNorm → fp16 output — feeds GEMM1
// ======================================================================
__global__ __launch_bounds__(256)
void ln_half_kernel(const float* __restrict__ x, const float* __restrict__ w,
                    const float* __restrict__ b, __half* __restrict__ y)
{
    const int tok = blockIdx.x;
    const int tid = threadIdx.x;
    float4 v = reinterpret_cast<const float4*>(x + (size_t)tok * DIM)[tid];
    float s  = v.x + v.y + v.z + v.w;
    float sq = v.x*v.x + v.y*v.y + v.z*v.z + v.w*v.w;
    #pragma unroll
    for (int o = 16; o > 0; o >>= 1) {
        s  += __shfl_xor_sync(0xffffffffu, s,  o);
        sq += __shfl_xor_sync(0xffffffffu, sq, o);
    }
    __shared__ float sa[8], sb[8];
    const int wid = tid >> 5, lid = tid & 31;
    if (lid == 0) { sa[wid] = s; sb[wid] = sq; }
    __syncthreads();
    if (tid < 32) {
        s  = (lid < 8) ? sa[lid] : 0.f;
        sq = (lid < 8) ? sb[lid] : 0.f;
        #pragma unroll
        for (int o = 4; o > 0; o >>= 1) {
            s  += __shfl_xor_sync(0xffffffffu, s,  o);
            sq += __shfl_xor_sync(0xffffffffu, sq, o);
        }
        if (lid == 0) { sa[0] = s; sb[0] = sq; }
    }
    __syncthreads();
    const float mean = sa[0] * (1.0f / DIM);
    const float var  = sb[0] * (1.0f / DIM) - mean * mean;
    const float rstd = rsqrtf(var + EPS);
    const float4 wv = reinterpret_cast<const float4*>(w)[tid];
    const float4 bv = reinterpret_cast<const float4*>(b)[tid];
    float o0 = (v.x - mean) * rstd * wv.x + bv.x;
    float o1 = (v.y - mean) * rstd * wv.y + bv.y;
    float o2 = (v.z - mean) * rstd * wv.z + bv.z;
    float o3 = (v.w - mean) * rstd * wv.w + bv.w;
    __half2* ph = reinterpret_cast<__half2*>(y + (size_t)tok * DIM);
    ph[tid * 2]     = __floats2half2_rn(o0, o1);
    ph[tid * 2 + 1] = __floats2half2_rn(o2, o3);
}

// ======================================================================
// fp32 -> fp16 conversion: w1 then w2 in one launch
// ======================================================================
#define W1_F4 (FF * DIM / 4)
#define W2_F4 (DIM * FF / 4)
__global__ __launch_bounds__(256)
void tofp16_both_kernel(const float* __restrict__ w1, __half* __restrict__ o1,
                        const float* __restrict__ w2, __half* __restrict__ o2)
{
    const int i = blockIdx.x * blockDim.x + threadIdx.x;
    const float* w = (i < W1_F4) ? w1 : w2;
    __half* o      = (i < W1_F4) ? o1 : o2;
    const int j    = (i < W1_F4) ? i : i - W1_F4;
    float4 v = reinterpret_cast<const float4*>(w)[j];
    reinterpret_cast<__half2*>(o)[2*j]   = __floats2half2_rn(v.x, v.y);
    reinterpret_cast<__half2*>(o)[2*j+1] = __floats2half2_rn(v.z, v.w);
}

// ======================================================================
// Chunked complex scan: s[l] = p*s[l-1] + h[l], s[-1]=last   (h in fp16)
// ======================================================================
__device__ __forceinline__ void get_p(const float* pre, const float* pim, int d,
                                      float& pr, float& pi) {
    const float prr = pre[d], pir = pim[d];
    const float mag = sqrtf(prr * prr + pir * pir);
    const float scale = (mag > 0.f) ? (tanhf(mag) / mag) : 0.f;
    pr = prr * scale; pi = pir * scale;
}

__global__ __launch_bounds__(128)
void scan_p1(const __half* __restrict__ h, const float* __restrict__ pre,
             const float* __restrict__ pim,
             float* __restrict__ cfr, float* __restrict__ cfi)
{
    const int d = blockIdx.x * 128 + threadIdx.x;
    const int c = blockIdx.y, b = blockIdx.z;
    float pr, pi; get_p(pre, pim, d, pr, pi);
    float sr = 0.f, si = 0.f;
    const __half* hp = h + ((size_t)b * SEQ + (size_t)c * CLEN) * DIM + d;
    #pragma unroll 8
    for (int l = 0; l < CLEN; ++l) {
        const float hv = __half2float(hp[(size_t)l * DIM]);
        const float nr = fmaf(pr, sr, fmaf(-pi, si, hv));
        const float ni = fmaf(pr, si, pi * sr);
        sr = nr; si = ni;
    }
    const int idx = (b * CHUNKS + c) * DIM + d;
    cfr[idx] = sr; cfi[idx] = si;
}

__global__ __launch_bounds__(128)
void scan_p2(const float* __restrict__ pre, const float* __restrict__ pim,
             const float* __restrict__ lre, const float* __restrict__ lim,
             const float* __restrict__ cfr, const float* __restrict__ cfi,
             float* __restrict__ csr, float* __restrict__ csi)
{
    const int d = blockIdx.x * 128 + threadIdx.x;
    const int b = blockIdx.y;
    float pr, pi; get_p(pre, pim, d, pr, pi);
    float ar = pr, ai = pi;       // p^CLEN by squaring (CLEN = 2^5)
    #pragma unroll
    for (int t = 0; t < 5; ++t) {
        const float nr = ar * ar - ai * ai;
        const float ni = 2.f * ar * ai;
        ar = nr; ai = ni;
    }
    float sr = lre[d], si = lim[d];
    #pragma unroll
    for (int c = 0; c < CHUNKS; ++c) {
        const int idx = (b * CHUNKS + c) * DIM + d;
        csr[idx] = sr; csi[idx] = si;
        const float fr = cfr[idx], fi = cfi[idx];
        const float nr = fmaf(ar, sr, fmaf(-ai, si, fr));
        const float ni = fmaf(ar, si, fmaf(ai, sr, fi));
        sr = nr; si = ni;
    }
}

__global__ __launch_bounds__(128)
void scan_p3(const __half* __restrict__ h, const float* __restrict__ x,
             const float* __restrict__ pre, const float* __restrict__ pim,
             const float* __restrict__ csr, const float* __restrict__ csi,
             const float* __restrict__ sc, float* __restrict__ x2)
{
    const int d = blockIdx.x * 128 + threadIdx.x;
    const int c = blockIdx.y, b = blockIdx.z;
    float pr, pi; get_p(pre, pim, d, pr, pi);
    const int idx = (b * CHUNKS + c) * DIM + d;
    float sr = csr[idx], si = csi[idx];
    const float scl = sc[d];
    const size_t base = ((size_t)b * SEQ + (size_t)c * CLEN) * DIM + d;
    const __half* hp = h + base;
    const float*  xp = x + base;
    float*        op = x2 + base;
    #pragma unroll 8
    for (int l = 0; l < CLEN; ++l) {
        const size_t off = (size_t)l * DIM;
        const float hv = __half2float(hp[off]);
        const float xv = xp[off];
        const float nr = fmaf(pr, sr, fmaf(-pi, si, hv));
        const float ni = fmaf(pr, si, pi * sr);
        sr = nr; si = ni;
        op[off] = fmaf(sr, scl, xv);
    }
}

// ======================================================================
// fp16 HMMA GEMM: C[M,N] = A[M,K] @ B[N,K]^T  (fp32 accumulate)
// 128x128x64 block tile, 256 threads, warp tile 32x64 (4x2 warps),
// 3-stage cp.async pipeline, XOR-8 swizzled 128B smem rows, 2 CTAs/SM.
// Grouped-serpentine CTA rasterization (G=8) for L2 locality.
// mode 0: hf = fp16(silu(acc + bias))        (GEMM1)
// mode 1: out = acc + bias + resid (fp32)    (GEMM2)
// ======================================================================
#define BM 128
#define BN 128
#define BK 64
#define STAGE_BYTES 32768         // A 16KB + B 16KB
#define GSMEM (3 * STAGE_BYTES)   // 96 KB

__global__ __launch_bounds__(256, 2)
void gemm_f16(const __half* __restrict__ A, const __half* __restrict__ B,
              const float* __restrict__ bias, const float* __restrict__ resid,
              float* __restrict__ outF, __half* __restrict__ outH,
              int M, int N, int K, int mode)
{
    extern __shared__ char smem[];
    const uint32_t sb = smem_u32(smem);
    const int tid  = threadIdx.x;
    const int lane = tid & 31;
    const int wid  = tid >> 5;
    const int wr   = wid & 3;       // warp M group (32 rows)
    const int wc   = wid >> 2;      // warp N group (64 cols)

    // grouped rasterization: groups of 8 M-tiles sweep N together
    const int nbx = gridDim.x;
    const int bid = blockIdx.y * nbx + blockIdx.x;
    const int gsz = 8 * nbx;
    const int g   = bid / gsz;
    const int rem = bid - g * gsz;
    const int by  = g * 8 + (rem & 7);
    const int bx  = rem >> 3;
    const int m0 = by * BM;
    const int n0 = bx * BN;

    // cp.async geometry: per stage, per thread: 4 chunks A + 4 chunks B (16B each)
    int ldrow[4], ldq[4]; uint32_t ldso[4];
    #pragma unroll
    for (int i = 0; i < 4; ++i) {
        const int idx = tid + 256 * i;   // 0..1023
        ldrow[i] = idx >> 3;
        ldq[i]   = idx & 7;
        ldso[i]  = (uint32_t)(ldrow[i] * 128 + ((ldq[i] ^ (ldrow[i] & 7)) << 4));
    }

    const int NKC = K >> 6;

    // ldmatrix geometry
    const int arow_b = wr * 32 + (lane & 15);
    const int brow_b = wc * 64 + (lane & 15);
    const int kh8    = lane >> 4;     // 0/1 -> k-halves chunk

    float acc[2][8][4];
    #pragma unroll
    for (int mi = 0; mi < 2; ++mi)
        #pragma unroll
        for (int n8 = 0; n8 < 8; ++n8)
            #pragma unroll
            for (int e = 0; e < 4; ++e) acc[mi][n8][e] = 0.f;

    auto load_stage = [&](int kt, int slot) {
        const uint32_t aB = sb + slot * STAGE_BYTES;
        const uint32_t bB = aB + 16384;
        const int k0 = kt * BK;
        #pragma unroll
        for (int i = 0; i < 4; ++i) {
            cp_async16(aB + ldso[i], A + (size_t)(m0 + ldrow[i]) * K + k0 + ldq[i] * 8);
            cp_async16(bB + ldso[i], B + (size_t)(n0 + ldrow[i]) * K + k0 + ldq[i] * 8);
        }
    };

    load_stage(0, 0); CP_COMMIT();
    load_stage(1, 1); CP_COMMIT();

    int slot = 0;
    for (int kt = 0; kt < NKC; ++kt) {
        CP_WAIT1();
        __syncthreads();
        if (kt + 2 < NKC) load_stage(kt + 2, (slot + 2) % 3);
        CP_COMMIT();

        const uint32_t aBase = sb + slot * STAGE_BYTES;
        const uint32_t bBase = aBase + 16384;
        #pragma unroll
        for (int s = 0; s < 4; ++s) {
            uint32_t af[2][4], bf[4][4];
            #pragma unroll
            for (int mi = 0; mi < 2; ++mi) {
                const int r = arow_b + mi * 16;
                const uint32_t q = (uint32_t)((s * 2 + kh8) ^ (r & 7));
                ldsm4(af[mi], aBase + (uint32_t)r * 128 + q * 16);
            }
            #pragma unroll
            for (int ni = 0; ni < 4; ++ni) {
                const int r = brow_b + ni * 16;
                const uint32_t q = (uint32_t)((s * 2 + kh8) ^ (r & 7));
                ldsm4(bf[ni], bBase + (uint32_t)r * 128 + q * 16);
            }
            #pragma unroll
            for (int mi = 0; mi < 2; ++mi)
                #pragma unroll
                for (int n8 = 0; n8 < 8; ++n8)
                    mma16816(acc[mi][n8], af[mi],
                             bf[n8 >> 1][n8 & 1], bf[n8 >> 1][(n8 & 1) + 2]);
        }
        slot = (slot + 1) % 3;
    }

    // ---- epilogue ----
    const int rq = lane >> 2;          // 0..7
    const int cq = (lane & 3) * 2;
    #pragma unroll
    for (int mi = 0; mi < 2; ++mi) {
        const int r0 = m0 + wr * 32 + mi * 16 + rq;
        #pragma unroll
        for (int n8 = 0; n8 < 8; ++n8) {
            const int c = n0 + wc * 64 + n8 * 8 + cq;
            const float b0 = bias[c], b1 = bias[c + 1];
            float d0 = acc[mi][n8][0] + b0;
            float d1 = acc[mi][n8][1] + b1;
            float d2 = acc[mi][n8][2] + b0;
            float d3 = acc[mi][n8][3] + b1;
            const size_t o0 = (size_t)r0 * N + c;
            const size_t o1 = (size_t)(r0 + 8) * N + c;
            if (mode == 0) {
                d0 *= 1.0f / (1.0f + expf(-d0));
                d1 *= 1.0f / (1.0f + expf(-d1));
                d2 *= 1.0f / (1.0f + expf(-d2));
                d3 *= 1.0f / (1.0f + expf(-d3));
                *reinterpret_cast<__half2*>(outH + o0) = __floats2half2_rn(d0, d1);
                *reinterpret_cast<__half2*>(outH + o1) = __floats2half2_rn(d2, d3);
            } else {
                const float2 rv0 = *reinterpret_cast<const float2*>(resid + o0);
                const float2 rv1 = *reinterpret_cast<const float2*>(resid + o1);
                float2 w0 = {d0 + rv0.x, d1 + rv0.y};
                float2 w1 = {d2 + rv1.x, d3 + rv1.y};
                *reinterpret_cast<float2*>(outF + o0) = w0;
                *reinterpret_cast<float2*>(outF + o1) = w1;
            }
        }
    }
}

// ======================================================================
// launch
// ======================================================================
extern "C" void kernel_launch(void* const* d_in, const int* in_sizes, int n_in,
                              void* d_out, int out_size)
{
    const float* x     = (const float*)d_in[0];
    const float* ln1_w = (const float*)d_in[1];
    const float* ln1_b = (const float*)d_in[2];
    const float* ln2_w = (const float*)d_in[3];
    const float* ln2_b = (const float*)d_in[4];
    const float* sclin = (const float*)d_in[5];
    const float* p_re  = (const float*)d_in[6];
    const float* p_im  = (const float*)d_in[7];
    const float* l_re  = (const float*)d_in[8];
    const float* l_im  = (const float*)d_in[9];
    const float* w1    = (const float*)d_in[10];
    const float* b1    = (const float*)d_in[11];
    const float* w2    = (const float*)d_in[12];
    const float* b2    = (const float*)d_in[13];
    float* out = (float*)d_out;

    float *x2, *cfr, *cfi, *csr, *csi;
    __half *h, *ah, *w1h, *w2h, *hf;
    cudaGetSymbolAddress((void**)&h,   g_h);
    cudaGetSymbolAddress((void**)&x2,  g_x2);
    cudaGetSymbolAddress((void**)&ah,  g_ah);
    cudaGetSymbolAddress((void**)&w1h, g_w1h);
    cudaGetSymbolAddress((void**)&w2h, g_w2h);
    cudaGetSymbolAddress((void**)&hf,  g_hf);
    cudaGetSymbolAddress((void**)&cfr, g_cfr);
    cudaGetSymbolAddress((void**)&cfi, g_cfi);
    cudaGetSymbolAddress((void**)&csr, g_csr);
    cudaGetSymbolAddress((void**)&csi, g_csi);

    cudaFuncSetAttribute(gemm_f16, cudaFuncAttributeMaxDynamicSharedMemorySize, GSMEM);

    // weight conversions (single fused launch)
    tofp16_both_kernel<<<(W1_F4 + W2_F4) / 256, 256>>>(w1, w1h, w2, w2h);

    // 1) h = silu(LN1(x))  (fp16)
    ln_silu_kernel<<<NTOK, 256>>>(x, ln1_w, ln1_b, h);

    // 2) chunked scan: x2 = Re(scan(h)) * sc_lin + x
    scan_p1<<<dim3(DIM / 128, CHUNKS, BATCH), 128>>>(h, p_re, p_im, cfr, cfi);
    scan_p2<<<dim3(DIM / 128, BATCH), 128>>>(p_re, p_im, l_re, l_im, cfr, cfi, csr, csi);
    scan_p3<<<dim3(DIM / 128, CHUNKS, BATCH), 128>>>(h, x, p_re, p_im, csr, csi, sclin, x2);

    // 3) LN2(x2) -> fp16
    ln_half_kernel<<<NTOK, 256>>>(x2, ln2_w, ln2_b, ah);

    // 4) hf = fp16(silu(ah @ w1^T + b1))   [8192,4096]
    gemm_f16<<<dim3(FF / BN, NTOK / BM), 256, GSMEM>>>(
        ah, w1h, b1, nullptr, nullptr, hf, NTOK, FF, DIM, 0);

    // 5) out = hf @ w2^T + b2 + x2         [8192,1024]
    gemm_f16<<<dim3(DIM / BN, NTOK / BM), 256, GSMEM>>>(
        hf, w2h, b2, x2, out, nullptr, NTOK, DIM, FF, 1);
}

// round 17
// speedup vs baseline: 1.0606x; 1.0012x over previous
#include <cuda_runtime.h>
#include <cuda_fp16.h>
#include <cstdint>
#include <math.h>

#define DIM   1024
#define FF    4096
#define BATCH 4
#define SEQ   2048
#define NTOK  (BATCH * SEQ)   // 8192
#define EPS   1e-5f

#define CHUNKS 64
#define CLEN   (SEQ / CHUNKS)  // 32

// ---------------- scratch (allocation-free: __device__ globals) ----------------
__device__ __half g_h [NTOK * DIM];          // LN1+silu output (fp16, scan input)
__device__ float  g_x2[NTOK * DIM];          // residual after sconv branch
__device__ __half g_ah [NTOK * DIM];         // LN2 out (fp16)
__device__ __half g_w1h[FF * DIM];           // w1 fp16
__device__ __half g_w2h[DIM * FF];           // w2 fp16
__device__ __half g_hf [(size_t)NTOK * FF];  // FFN hidden (fp16)
__device__ float  g_cfr[BATCH * CHUNKS * DIM];
__device__ float  g_cfi[BATCH * CHUNKS * DIM];
__device__ float  g_csr[BATCH * CHUNKS * DIM];
__device__ float  g_csi[BATCH * CHUNKS * DIM];

// ======================== PTX helpers (baseline ISA, sm_80+) ========================
__device__ __forceinline__ uint32_t smem_u32(const void* p) {
    uint32_t a;
    asm("{ .reg .u64 t; cvta.to.shared.u64 t, %1; cvt.u32.u64 %0, t; }" : "=r"(a) : "l"(p));
    return a;
}
__device__ __forceinline__ void cp_async16(uint32_t s, const void* g) {
    asm volatile("cp.async.cg.shared.global [%0], [%1], 16;" :: "r"(s), "l"(g) : "memory");
}
#define CP_COMMIT() asm volatile("cp.async.commit_group;" ::: "memory")
#define CP_WAIT1()  asm volatile("cp.async.wait_group 1;" ::: "memory")

__device__ __forceinline__ void ldsm4(uint32_t* r, uint32_t addr) {
    asm volatile("ldmatrix.sync.aligned.m8n8.x4.shared.b16 {%0,%1,%2,%3}, [%4];"
                 : "=r"(r[0]), "=r"(r[1]), "=r"(r[2]), "=r"(r[3]) : "r"(addr));
}
__device__ __forceinline__ void mma16816(float* d, const uint32_t* a,
                                         uint32_t b0, uint32_t b1) {
    asm volatile(
        "mma.sync.aligned.m16n8k16.row.col.f32.f16.f16.f32 "
        "{%0,%1,%2,%3}, {%4,%5,%6,%7}, {%8,%9}, {%0,%1,%2,%3};"
        : "+f"(d[0]), "+f"(d[1]), "+f"(d[2]), "+f"(d[3])
        : "r"(a[0]), "r"(a[1]), "r"(a[2]), "r"(a[3]), "r"(b0), "r"(b1));
}

// ======================================================================
// LayerNorm + SiLU (fp16 out) — feeds the scan
// ======================================================================
__global__ __launch_bounds__(256)
void ln_silu_kernel(const float* __restrict__ x, const float* __restrict__ w,
                    const float* __restrict__ b, __half* __restrict__ y)
{
    const int tok = blockIdx.x;
    const int tid = threadIdx.x;
    float4 v = reinterpret_cast<const float4*>(x + (size_t)tok * DIM)[tid];
    float s  = v.x + v.y + v.z + v.w;
    float sq = v.x*v.x + v.y*v.y + v.z*v.z + v.w*v.w;
    #pragma unroll
    for (int o = 16; o > 0; o >>= 1) {
        s  += __shfl_xor_sync(0xffffffffu, s,  o);
        sq += __shfl_xor_sync(0xffffffffu, sq, o);
    }
    __shared__ float sa[8], sb[8];
    const int wid = tid >> 5, lid = tid & 31;
    if (lid == 0) { sa[wid] = s; sb[wid] = sq; }
    __syncthreads();
    if (tid < 32) {
        s  = (lid < 8) ? sa[lid] : 0.f;
        sq = (lid < 8) ? sb[lid] : 0.f;
        #pragma unroll
        for (int o = 4; o > 0; o >>= 1) {
            s  += __shfl_xor_sync(0xffffffffu, s,  o);
            sq += __shfl_xor_sync(0xffffffffu, sq, o);
        }
        if (lid == 0) { sa[0] = s; sb[0] = sq; }
    }
    __syncthreads();
    const float mean = sa[0] * (1.0f / DIM);
    const float var  = sb[0] * (1.0f / DIM) - mean * mean;
    const float rstd = rsqrtf(var + EPS);
    const float4 wv = reinterpret_cast<const float4*>(w)[tid];
    const float4 bv = reinterpret_cast<const float4*>(b)[tid];
    float o0 = (v.x - mean) * rstd * wv.x + bv.x;
    float o1 = (v.y - mean) * rstd * wv.y + bv.y;
    float o2 = (v.z - mean) * rstd * wv.z + bv.z;
    float o3 = (v.w - mean) * rstd * wv.w + bv.w;
    o0 *= 1.0f / (1.0f + expf(-o0));
    o1 *= 1.0f / (1.0f + expf(-o1));
    o2 *= 1.0f / (1.0f + expf(-o2));
    o3 *= 1.0f / (1.0f + expf(-o3));
    __half2* ph = reinterpret_cast<__half2*>(y + (size_t)tok * DIM);
    ph[tid * 2]     = __floats2half2_rn(o0, o1);
    ph[tid * 2 + 1] = __floats2half2_rn(o2, o3);
}

// ======================================================================
// LayerNorm → fp16 output — feeds GEMM1
// ======================================================================
__global__ __launch_bounds__(256)
void ln_half_kernel(const float* __restrict__ x, const float* __restrict__ w,
                    const float* __restrict__ b, __half* __restrict__ y)
{
    const int tok = blockIdx.x;
    const int tid = threadIdx.x;
    float4 v = reinterpret_cast<const float4*>(x + (size_t)tok * DIM)[tid];
    float s  = v.x + v.y + v.z + v.w;
    float sq = v.x*v.x + v.y*v.y + v.z*v.z + v.w*v.w;
    #pragma unroll
    for (int o = 16; o > 0; o >>= 1) {
        s  += __shfl_xor_sync(0xffffffffu, s,  o);
        sq += __shfl_xor_sync(0xffffffffu, sq, o);
    }
    __shared__ float sa[8], sb[8];
    const int wid = tid >> 5, lid = tid & 31;
    if (lid == 0) { sa[wid] = s; sb[wid] = sq; }
    __syncthreads();
    if (tid < 32) {
        s  = (lid < 8) ? sa[lid] : 0.f;
        sq = (lid < 8) ? sb[lid] : 0.f;
        #pragma unroll
        for (int o = 4; o > 0; o >>= 1) {
            s  += __shfl_xor_sync(0xffffffffu, s,  o);
            sq += __shfl_xor_sync(0xffffffffu, sq, o);
        }
        if (lid == 0) { sa[0] = s; sb[0] = sq; }
    }
    __syncthreads();
    const float mean = sa[0] * (1.0f / DIM);
    const float var  = sb[0] * (1.0f / DIM) - mean * mean;
    const float rstd = rsqrtf(var + EPS);
    const float4 wv = reinterpret_cast<const float4*>(w)[tid];
    const float4 bv = reinterpret_cast<const float4*>(b)[tid];
    float o0 = (v.x - mean) * rstd * wv.x + bv.x;
    float o1 = (v.y - mean) * rstd * wv.y + bv.y;
    float o2 = (v.z - mean) * rstd * wv.z + bv.z;
    float o3 = (v.w - mean) * rstd * wv.w + bv.w;
    __half2* ph = reinterpret_cast<__half2*>(y + (size_t)tok * DIM);
    ph[tid * 2]     = __floats2half2_rn(o0, o1);
    ph[tid * 2 + 1] = __floats2half2_rn(o2, o3);
}

// ======================================================================
// fp32 -> fp16 conversion: w1 then w2 in one launch
// ======================================================================
#define W1_F4 (FF * DIM / 4)
#define W2_F4 (DIM * FF / 4)
__global__ __launch_bounds__(256)
void tofp16_both_kernel(const float* __restrict__ w1, __half* __restrict__ o1,
                        const float* __restrict__ w2, __half* __restrict__ o2)
{
    const int i = blockIdx.x * blockDim.x + threadIdx.x;
    const float* w = (i < W1_F4) ? w1 : w2;
    __half* o      = (i < W1_F4) ? o1 : o2;
    const int j    = (i < W1_F4) ? i : i - W1_F4;
    float4 v = reinterpret_cast<const float4*>(w)[j];
    reinterpret_cast<__half2*>(o)[2*j]   = __floats2half2_rn(v.x, v.y);
    reinterpret_cast<__half2*>(o)[2*j+1] = __floats2half2_rn(v.z, v.w);
}

// ======================================================================
// Chunked complex scan: s[l] = p*s[l-1] + h[l], s[-1]=last   (h in fp16)
// ======================================================================
__device__ __forceinline__ void get_p(const float* pre, const float* pim, int d,
                                      float& pr, float& pi) {
    const float prr = pre[d], pir = pim[d];
    const float mag = sqrtf(prr * prr + pir * pir);
    const float scale = (mag > 0.f) ? (tanhf(mag) / mag) : 0.f;
    pr = prr * scale; pi = pir * scale;
}

__global__ __launch_bounds__(128)
void scan_p1(const __half* __restrict__ h, const float* __restrict__ pre,
             const float* __restrict__ pim,
             float* __restrict__ cfr, float* __restrict__ cfi)
{
    const int d = blockIdx.x * 128 + threadIdx.x;
    const int c = blockIdx.y, b = blockIdx.z;
    float pr, pi; get_p(pre, pim, d, pr, pi);
    float sr = 0.f, si = 0.f;
    const __half* hp = h + ((size_t)b * SEQ + (size_t)c * CLEN) * DIM + d;
    #pragma unroll 8
    for (int l = 0; l < CLEN; ++l) {
        const float hv = __half2float(hp[(size_t)l * DIM]);
        const float nr = fmaf(pr, sr, fmaf(-pi, si, hv));
        const float ni = fmaf(pr, si, pi * sr);
        sr = nr; si = ni;
    }
    const int idx = (b * CHUNKS + c) * DIM + d;
    cfr[idx] = sr; cfi[idx] = si;
}

// phase 2: prefetch all chunk-finals into registers (independent loads),
// then run the serial carry combine entirely from registers.
__global__ __launch_bounds__(128)
void scan_p2(const float* __restrict__ pre, const float* __restrict__ pim,
             const float* __restrict__ lre, const float* __restrict__ lim,
             const float* __restrict__ cfr, const float* __restrict__ cfi,
             float* __restrict__ csr, float* __restrict__ csi)
{
    const int d = blockIdx.x * 128 + threadIdx.x;
    const int b = blockIdx.y;
    float pr, pi; get_p(pre, pim, d, pr, pi);
    float ar = pr, ai = pi;       // p^CLEN by squaring (CLEN = 2^5)
    #pragma unroll
    for (int t = 0; t < 5; ++t) {
        const float nr = ar * ar - ai * ai;
        const float ni = 2.f * ar * ai;
        ar = nr; ai = ni;
    }

    const int base = b * CHUNKS * DIM + d;

    // phase A: batch-prefetch (MLP = 2*CHUNKS)
    float fr[CHUNKS], fi[CHUNKS];
    #pragma unroll
    for (int c = 0; c < CHUNKS; ++c) {
        fr[c] = cfr[base + c * DIM];
        fi[c] = cfi[base + c * DIM];
    }

    // phase B: serial combine from registers + store carries
    float sr = lre[d], si = lim[d];
    #pragma unroll
    for (int c = 0; c < CHUNKS; ++c) {
        csr[base + c * DIM] = sr;
        csi[base + c * DIM] = si;
        const float nr = fmaf(ar, sr, fmaf(-ai, si, fr[c]));
        const float ni = fmaf(ar, si, fmaf(ai, sr, fi[c]));
        sr = nr; si = ni;
    }
}

__global__ __launch_bounds__(128)
void scan_p3(const __half* __restrict__ h, const float* __restrict__ x,
             const float* __restrict__ pre, const float* __restrict__ pim,
             const float* __restrict__ csr, const float* __restrict__ csi,
             const float* __restrict__ sc, float* __restrict__ x2)
{
    const int d = blockIdx.x * 128 + threadIdx.x;
    const int c = blockIdx.y, b = blockIdx.z;
    float pr, pi; get_p(pre, pim, d, pr, pi);
    const int idx = (b * CHUNKS + c) * DIM + d;
    float sr = csr[idx], si = csi[idx];
    const float scl = sc[d];
    const size_t base = ((size_t)b * SEQ + (size_t)c * CLEN) * DIM + d;
    const __half* hp = h + base;
    const float*  xp = x + base;
    float*        op = x2 + base;
    #pragma unroll 8
    for (int l = 0; l < CLEN; ++l) {
        const size_t off = (size_t)l * DIM;
        const float hv = __half2float(hp[off]);
        const float xv = xp[off];
        const float nr = fmaf(pr, sr, fmaf(-pi, si, hv));
        const float ni = fmaf(pr, si, pi * sr);
        sr = nr; si = ni;
        op[off] = fmaf(sr, scl, xv);
    }
}

// ======================================================================
// fp16 HMMA GEMM: C[M,N] = A[M,K] @ B[N,K]^T  (fp32 accumulate)
// 128x128x64 block tile, 256 threads, warp tile 32x64 (4x2 warps),
// 3-stage cp.async pipeline, XOR-8 swizzled 128B smem rows, 2 CTAs/SM.
// Grouped-serpentine CTA rasterization (G=8) for L2 locality.
// mode 0: hf = fp16(silu(acc + bias))        (GEMM1)
// mode 1: out = acc + bias + resid (fp32)    (GEMM2)
// ======================================================================
#define BM 128
#define BN 128
#define BK 64
#define STAGE_BYTES 32768         // A 16KB + B 16KB
#define GSMEM (3 * STAGE_BYTES)   // 96 KB

__global__ __launch_bounds__(256, 2)
void gemm_f16(const __half* __restrict__ A, const __half* __restrict__ B,
              const float* __restrict__ bias, const float* __restrict__ resid,
              float* __restrict__ outF, __half* __restrict__ outH,
              int M, int N, int K, int mode)
{
    extern __shared__ char smem[];
    const uint32_t sb = smem_u32(smem);
    const int tid  = threadIdx.x;
    const int lane = tid & 31;
    const int wid  = tid >> 5;
    const int wr   = wid & 3;       // warp M group (32 rows)
    const int wc   = wid >> 2;      // warp N group (64 cols)

    // grouped rasterization: groups of 8 M-tiles sweep N together
    const int nbx = gridDim.x;
    const int bid = blockIdx.y * nbx + blockIdx.x;
    const int gsz = 8 * nbx;
    const int g   = bid / gsz;
    const int rem = bid - g * gsz;
    const int by  = g * 8 + (rem & 7);
    const int bx  = rem >> 3;
    const int m0 = by * BM;
    const int n0 = bx * BN;

    // cp.async geometry: per stage, per thread: 4 chunks A + 4 chunks B (16B each)
    int ldrow[4], ldq[4]; uint32_t ldso[4];
    #pragma unroll
    for (int i = 0; i < 4; ++i) {
        const int idx = tid + 256 * i;   // 0..1023
        ldrow[i] = idx >> 3;
        ldq[i]   = idx & 7;
        ldso[i]  = (uint32_t)(ldrow[i] * 128 + ((ldq[i] ^ (ldrow[i] & 7)) << 4));
    }

    const int NKC = K >> 6;

    // ldmatrix geometry
    const int arow_b = wr * 32 + (lane & 15);
    const int brow_b = wc * 64 + (lane & 15);
    const int kh8    = lane >> 4;     // 0/1 -> k-halves chunk

    float acc[2][8][4];
    #pragma unroll
    for (int mi = 0; mi < 2; ++mi)
        #pragma unroll
        for (int n8 = 0; n8 < 8; ++n8)
            #pragma unroll
            for (int e = 0; e < 4; ++e) acc[mi][n8][e] = 0.f;

    auto load_stage = [&](int kt, int slot) {
        const uint32_t aB = sb + slot * STAGE_BYTES;
        const uint32_t bB = aB + 16384;
        const int k0 = kt * BK;
        #pragma unroll
        for (int i = 0; i < 4; ++i) {
            cp_async16(aB + ldso[i], A + (size_t)(m0 + ldrow[i]) * K + k0 + ldq[i] * 8);
            cp_async16(bB + ldso[i], B + (size_t)(n0 + ldrow[i]) * K + k0 + ldq[i] * 8);
        }
    };

    load_stage(0, 0); CP_COMMIT();
    load_stage(1, 1); CP_COMMIT();

    int slot = 0;
    for (int kt = 0; kt < NKC; ++kt) {
        CP_WAIT1();
        __syncthreads();
        if (kt + 2 < NKC) load_stage(kt + 2, (slot + 2) % 3);
        CP_COMMIT();

        const uint32_t aBase = sb + slot * STAGE_BYTES;
        const uint32_t bBase = aBase + 16384;
        #pragma unroll
        for (int s = 0; s < 4; ++s) {
            uint32_t af[2][4], bf[4][4];
            #pragma unroll
            for (int mi = 0; mi < 2; ++mi) {
                const int r = arow_b + mi * 16;
                const uint32_t q = (uint32_t)((s * 2 + kh8) ^ (r & 7));
                ldsm4(af[mi], aBase + (uint32_t)r * 128 + q * 16);
            }
            #pragma unroll
            for (int ni = 0; ni < 4; ++ni) {
                const int r = brow_b + ni * 16;
                const uint32_t q = (uint32_t)((s * 2 + kh8) ^ (r & 7));
                ldsm4(bf[ni], bBase + (uint32_t)r * 128 + q * 16);
            }
            #pragma unroll
            for (int mi = 0; mi < 2; ++mi)
                #pragma unroll
                for (int n8 = 0; n8 < 8; ++n8)
                    mma16816(acc[mi][n8], af[mi],
                             bf[n8 >> 1][n8 & 1], bf[n8 >> 1][(n8 & 1) + 2]);
        }
        slot = (slot + 1) % 3;
    }

    // ---- epilogue ----
    const int rq = lane >> 2;          // 0..7
    const int cq = (lane & 3) * 2;
    #pragma unroll
    for (int mi = 0; mi < 2; ++mi) {
        const int r0 = m0 + wr * 32 + mi * 16 + rq;
        #pragma unroll
        for (int n8 = 0; n8 < 8; ++n8) {
            const int c = n0 + wc * 64 + n8 * 8 + cq;
            const float b0 = bias[c], b1 = bias[c + 1];
            float d0 = acc[mi][n8][0] + b0;
            float d1 = acc[mi][n8][1] + b1;
            float d2 = acc[mi][n8][2] + b0;
            float d3 = acc[mi][n8][3] + b1;
            const size_t o0 = (size_t)r0 * N + c;
            const size_t o1 = (size_t)(r0 + 8) * N + c;
            if (mode == 0) {
                d0 *= 1.0f / (1.0f + expf(-d0));
                d1 *= 1.0f / (1.0f + expf(-d1));
                d2 *= 1.0f / (1.0f + expf(-d2));
                d3 *= 1.0f / (1.0f + expf(-d3));
                *reinterpret_cast<__half2*>(outH + o0) = __floats2half2_rn(d0, d1);
                *reinterpret_cast<__half2*>(outH + o1) = __floats2half2_rn(d2, d3);
            } else {
                const float2 rv0 = *reinterpret_cast<const float2*>(resid + o0);
                const float2 rv1 = *reinterpret_cast<const float2*>(resid + o1);
                float2 w0 = {d0 + rv0.x, d1 + rv0.y};
                float2 w1 = {d2 + rv1.x, d3 + rv1.y};
                *reinterpret_cast<float2*>(outF + o0) = w0;
                *reinterpret_cast<float2*>(outF + o1) = w1;
            }
        }
    }
}

// ======================================================================
// launch
// ======================================================================
extern "C" void kernel_launch(void* const* d_in, const int* in_sizes, int n_in,
                              void* d_out, int out_size)
{
    const float* x     = (const float*)d_in[0];
    const float* ln1_w = (const float*)d_in[1];
    const float* ln1_b = (const float*)d_in[2];
    const float* ln2_w = (const float*)d_in[3];
    const float* ln2_b = (const float*)d_in[4];
    const float* sclin = (const float*)d_in[5];
    const float* p_re  = (const float*)d_in[6];
    const float* p_im  = (const float*)d_in[7];
    const float* l_re  = (const float*)d_in[8];
    const float* l_im  = (const float*)d_in[9];
    const float* w1    = (const float*)d_in[10];
    const float* b1    = (const float*)d_in[11];
    const float* w2    = (const float*)d_in[12];
    const float* b2    = (const float*)d_in[13];
    float* out = (float*)d_out;

    float *x2, *cfr, *cfi, *csr, *csi;
    __half *h, *ah, *w1h, *w2h, *hf;
    cudaGetSymbolAddress((void**)&h,   g_h);
    cudaGetSymbolAddress((void**)&x2,  g_x2);
    cudaGetSymbolAddress((void**)&ah,  g_ah);
    cudaGetSymbolAddress((void**)&w1h, g_w1h);
    cudaGetSymbolAddress((void**)&w2h, g_w2h);
    cudaGetSymbolAddress((void**)&hf,  g_hf);
    cudaGetSymbolAddress((void**)&cfr, g_cfr);
    cudaGetSymbolAddress((void**)&cfi, g_cfi);
    cudaGetSymbolAddress((void**)&csr, g_csr);
    cudaGetSymbolAddress((void**)&csi, g_csi);

    cudaFuncSetAttribute(gemm_f16, cudaFuncAttributeMaxDynamicSharedMemorySize, GSMEM);

    // weight conversions (single fused launch)
    tofp16_both_kernel<<<(W1_F4 + W2_F4) / 256, 256>>>(w1, w1h, w2, w2h);

    // 1) h = silu(LN1(x))  (fp16)
    ln_silu_kernel<<<NTOK, 256>>>(x, ln1_w, ln1_b, h);

    // 2) chunked scan: x2 = Re(scan(h)) * sc_lin + x
    scan_p1<<<dim3(DIM / 128, CHUNKS, BATCH), 128>>>(h, p_re, p_im, cfr, cfi);
    scan_p2<<<dim3(DIM / 128, BATCH), 128>>>(p_re, p_im, l_re, l_im, cfr, cfi, csr, csi);
    scan_p3<<<dim3(DIM / 128, CHUNKS, BATCH), 128>>>(h, x, p_re, p_im, csr, csi, sclin, x2);

    // 3) LN2(x2) -> fp16
    ln_half_kernel<<<NTOK, 256>>>(x2, ln2_w, ln2_b, ah);

    // 4) hf = fp16(silu(ah @ w1^T + b1))   [8192,4096]
    gemm_f16<<<dim3(FF / BN, NTOK / BM), 256, GSMEM>>>(
        ah, w1h, b1, nullptr, nullptr, hf, NTOK, FF, DIM, 0);

    // 5) out = hf @ w2^T + b2 + x2         [8192,1024]
    gemm_f16<<<dim3(DIM / BN, NTOK / BM), 256, GSMEM>>>(
        hf, w2h, b2, x2, out, nullptr, NTOK, DIM, FF, 1);
}